// round 7
// baseline (speedup 1.0000x reference)
#include <cuda_runtime.h>
#include <math.h>

// Problem constants
#define B_   4
#define CIN  256
#define CKEY 448
#define HW   4096          // N = 64*64 tokens
#define NEGV (-1e15f)

#define KCH   32           // K chunk width (floats)
#define KPAD  36           // padded row stride for K chunk buffers
#define NCHUNK (CKEY / KCH) // 14
#define NTILE (B_ * (HW / 32))   // 512 query tiles
#define FLASH_BLOCKS 152

// ---------------- scratch (static device globals; no allocation) ----------------
__device__ float g_Fq[B_ * HW * CKEY];    // [b][n][ck]  query projection
__device__ float g_Kt[B_ * HW * CKEY];    // [b][n][ck]  key projection
__device__ float g_Hvv[B_ * HW * 2 * CIN];// [b][n][2c]  value proj interleaved (v, v^2)
__device__ float g_mean[B_ * HW * CIN];   // [b][n][c]
__device__ float g_std[B_ * HW * CIN];    // [b][n][c]
__device__ float g_cmean[B_ * CIN];
__device__ float g_crstd[B_ * CIN];
__device__ unsigned int g_ticket;

// ---------------- packed f32x2 helpers (FFMA2 path — ptxas never emits these from C++)
__device__ __forceinline__ unsigned long long pack2(float a, float b) {
    unsigned long long r;
    asm("mov.b64 %0, {%1, %2};" : "=l"(r) : "f"(a), "f"(b));
    return r;
}
__device__ __forceinline__ void fma2(unsigned long long& d, unsigned long long a, unsigned long long b) {
    asm("fma.rn.f32x2 %0, %1, %2, %3;" : "=l"(d) : "l"(a), "l"(b), "l"(d));
}
__device__ __forceinline__ unsigned long long mul2(unsigned long long a, unsigned long long b) {
    unsigned long long d;
    asm("mul.rn.f32x2 %0, %1, %2;" : "=l"(d) : "l"(a), "l"(b));
    return d;
}
__device__ __forceinline__ float2 unpack2(unsigned long long v) {
    float2 r;
    asm("mov.b64 {%0, %1}, %2;" : "=f"(r.x), "=f"(r.y) : "l"(v));
    return r;
}

// ---------------- cp.async helpers
__device__ __forceinline__ void cpa16(void* smem_dst, const void* gsrc) {
    unsigned sa = (unsigned)__cvta_generic_to_shared(smem_dst);
    asm volatile("cp.async.cg.shared.global [%0], [%1], 16;" :: "r"(sa), "l"(gsrc));
}
#define CPA_COMMIT()  asm volatile("cp.async.commit_group;")
#define CPA_WAIT(n)   asm volatile("cp.async.wait_group %0;" :: "n"(n))

// ---------------- 1x1 conv == GEMM:  out[b][n][o] = sum_c x[b][c][n] * W[o][c] + bias[o]
__global__ __launch_bounds__(256) void proj_kernel(
    const float* __restrict__ x, const float* __restrict__ W,
    const float* __restrict__ bias, float* __restrict__ out, int C, int O, int interleave)
{
    __shared__ float As[16][64];      // [kc][n]
    __shared__ float Bs[16][68];      // [kc][o] padded
    const int t  = threadIdx.x;
    const int ty = t >> 4, tx = t & 15;
    const int n0 = blockIdx.x * 64, o0 = blockIdx.y * 64, b = blockIdx.z;
    const float* xb = x + (size_t)b * C * HW;

    unsigned long long acc2[4][2];
#pragma unroll
    for (int i = 0; i < 4; i++) { acc2[i][0] = 0ull; acc2[i][1] = 0ull; }

    for (int c0 = 0; c0 < C; c0 += 16) {
#pragma unroll
        for (int j = 0; j < 4; j++) {
            int idx = t + j * 256;                       // 0..1023
            As[idx >> 6][idx & 63] = xb[(size_t)(c0 + (idx >> 6)) * HW + n0 + (idx & 63)];
        }
#pragma unroll
        for (int j = 0; j < 4; j++) {
            int idx = t + j * 256;
            int kk = idx & 15, o = idx >> 4;
            Bs[kk][o] = W[(size_t)(o0 + o) * C + c0 + kk];
        }
        __syncthreads();
#pragma unroll
        for (int kk = 0; kk < 16; kk++) {
            ulonglong2 bp = *(const ulonglong2*)&Bs[kk][tx * 4];
#pragma unroll
            for (int i = 0; i < 4; i++) {
                float a = As[kk][ty + 16 * i];
                unsigned long long aa = pack2(a, a);
                fma2(acc2[i][0], aa, bp.x);
                fma2(acc2[i][1], aa, bp.y);
            }
        }
        __syncthreads();
    }
    float4 bj = *(const float4*)&bias[o0 + tx * 4];
#pragma unroll
    for (int i = 0; i < 4; i++) {
        float2 l0 = unpack2(acc2[i][0]);
        float2 l1 = unpack2(acc2[i][1]);
        float4 r;
        r.x = l0.x + bj.x; r.y = l0.y + bj.y; r.z = l1.x + bj.z; r.w = l1.y + bj.w;
        size_t row = (size_t)(b * HW) + n0 + ty + 16 * i;
        if (!interleave) {
            *(float4*)&out[row * O + o0 + tx * 4] = r;
        } else {
            float4 lo, hi;
            lo.x = r.x; lo.y = r.x * r.x; lo.z = r.y; lo.w = r.y * r.y;
            hi.x = r.z; hi.y = r.z * r.z; hi.z = r.w; hi.w = r.w * r.w;
            size_t base = row * (2 * O) + 2 * (o0 + tx * 4);
            *(float4*)&out[base]     = lo;
            *(float4*)&out[base + 4] = hi;
        }
    }
}

// ---------------- content per-(b,c) mean / rstd (unbiased var, eps inside sqrt)
__global__ __launch_bounds__(256) void stats_kernel(const float* __restrict__ content)
{
    const int c = blockIdx.x, b = blockIdx.y;
    const float* p = content + ((size_t)(b * CIN + c)) * HW;
    float s = 0.f, s2 = 0.f;
    for (int i = threadIdx.x; i < HW; i += 256) { float v = p[i]; s += v; s2 += v * v; }
#pragma unroll
    for (int o = 16; o > 0; o >>= 1) {
        s  += __shfl_down_sync(0xffffffffu, s,  o);
        s2 += __shfl_down_sync(0xffffffffu, s2, o);
    }
    __shared__ float sh[2][8];
    if ((threadIdx.x & 31) == 0) { sh[0][threadIdx.x >> 5] = s; sh[1][threadIdx.x >> 5] = s2; }
    __syncthreads();
    if (threadIdx.x == 0) {
        float S = 0.f, S2 = 0.f;
#pragma unroll
        for (int w = 0; w < 8; w++) { S += sh[0][w]; S2 += sh[1][w]; }
        float mean = S / (float)HW;
        float var  = (S2 - S * S / (float)HW) / (float)(HW - 1);
        g_cmean[b * CIN + c] = mean;
        g_crstd[b * CIN + c] = rsqrtf(var + 1e-5f);
    }
}

__global__ void ticket_reset_kernel() { g_ticket = 0u; }

// ---------------- persistent flash attention, dual (mean, m2) accumulators
// cp.async triple-buffered K chunks; V tile + style mask streamed async.
// grid = FLASH_BLOCKS persistent CTAs; atomic ticket -> (b, q-tile).
struct FlashSmem {
    float Qs[32 * CKEY];          // [m][c]
    float Ks[3 * 64 * KPAD];      // 3 chunk buffers [k][KCH] padded
    float Vs[64 * 512];           // [k][2c] interleaved (v, v^2)
    float Ssh[32 * 65];           // [m][k] padded
    float rowmax[32], rowsum[32], rscale[32];
    int   cm[32];
    int   Msk[64];
    unsigned int ticket;
};

__global__ __launch_bounds__(256, 1) void flash_kernel(
    const int* __restrict__ cmaskg, const int* __restrict__ smaskg)
{
    extern __shared__ __align__(16) char raw[];
    FlashSmem& sm = *reinterpret_cast<FlashSmem*>(raw);
    const int t    = threadIdx.x;
    const int lane = t & 31;
    const int w    = t >> 5;
    const int pair = w >> 1;
    const int qb   = pair * 8;        // score phase: 8 query rows per warp
    const int ko   = (w & 1) * 32;    // score phase: 32-key half per warp
    const int r8   = t >> 3;          // softmax row (0..31)
    const int seg  = t & 7;           // softmax segment

    while (true) {
        if (t == 0) sm.ticket = atomicAdd(&g_ticket, 1u);
        __syncthreads();               // ticket visible; orders vs prior tile's smem use
        const unsigned int tile = sm.ticket;
        if (tile >= NTILE) break;
        const int b  = tile >> 7;
        const int q0 = (tile & 127) * 32;

        // ---- per-tile init
        {
            const float* src = g_Fq + ((size_t)(b * HW + q0)) * CKEY;
            for (int i4 = t; i4 < 32 * CKEY / 4; i4 += 256)
                *(float4*)&sm.Qs[i4 * 4] = *(const float4*)&src[i4 * 4];
        }
        if (t < 32) {
            sm.cm[t]     = cmaskg[b * HW + q0 + t];
            sm.rowmax[t] = -INFINITY;
            sm.rowsum[t] = 0.f;
        }
        unsigned long long acc[4][4][2];
#pragma unroll
        for (int i = 0; i < 4; i++)
#pragma unroll
            for (int j = 0; j < 4; j++) { acc[i][j][0] = 0ull; acc[i][j][1] = 0ull; }

        const size_t kbase = (size_t)(b * HW) * CKEY;
        const size_t vbase = (size_t)(b * HW) * 512;

        for (int k0 = 0; k0 < HW; k0 += 64) {
            // ---- issue async groups: G0 = K chunk0, G1 = K chunk1, G2 = V tile + mask
#pragma unroll
            for (int cpre = 0; cpre < 2; cpre++) {
                float* kb = &sm.Ks[cpre * 64 * KPAD];
#pragma unroll
                for (int j = 0; j < 2; j++) {
                    int idx = t + j * 256;          // 0..511
                    int row = idx >> 3, sg = idx & 7;
                    cpa16(&kb[row * KPAD + sg * 4],
                          &g_Kt[kbase + (size_t)(k0 + row) * CKEY + cpre * KCH + sg * 4]);
                }
                CPA_COMMIT();
            }
            {
#pragma unroll
                for (int j = 0; j < 32; j++) {
                    int idx = t + j * 256;          // 0..8191
                    int row = idx >> 7, sg = idx & 127;
                    cpa16(&sm.Vs[row * 512 + sg * 4],
                          &g_Hvv[vbase + (size_t)(k0 + row) * 512 + sg * 4]);
                }
                if (t < 16) cpa16(&sm.Msk[t * 4], &smaskg[b * HW + k0 + t * 4]);
                CPA_COMMIT();
            }

            // ---- S = Q K^T over 14 pipelined 32-wide chunks
            unsigned long long sv2[8];
#pragma unroll
            for (int i = 0; i < 8; i++) sv2[i] = 0ull;

            for (int ci = 0; ci < NCHUNK; ci++) {
                if (ci < 2)               CPA_WAIT(2);
                else if (ci < NCHUNK - 1) CPA_WAIT(1);
                else                      CPA_WAIT(0);
                __syncthreads();           // cross-thread visibility of retired groups
                if (ci + 2 < NCHUNK) {     // prefetch chunk ci+2 into buffer (ci+2)%3
                    float* kb = &sm.Ks[((ci + 2) % 3) * 64 * KPAD];
#pragma unroll
                    for (int j = 0; j < 2; j++) {
                        int idx = t + j * 256;
                        int row = idx >> 3, sg = idx & 7;
                        cpa16(&kb[row * KPAD + sg * 4],
                              &g_Kt[kbase + (size_t)(k0 + row) * CKEY + (ci + 2) * KCH + sg * 4]);
                    }
                    CPA_COMMIT();
                }
                const float* kb = &sm.Ks[(ci % 3) * 64 * KPAD];
                const int cc = ci * KCH;
#pragma unroll
                for (int c = 0; c < KCH; c += 4) {
                    ulonglong2 ka = *(const ulonglong2*)&kb[(ko + lane) * KPAD + c];
#pragma unroll
                    for (int i = 0; i < 8; i++) {
                        ulonglong2 q2 = *(const ulonglong2*)&sm.Qs[(qb + i) * CKEY + cc + c];
                        fma2(sv2[i], q2.x, ka.x);
                        fma2(sv2[i], q2.y, ka.y);
                    }
                }
            }

            // ---- mask + store scores (mask staged via G2, long retired)
            {
                int km = (sm.Msk[ko + lane] == 0);
#pragma unroll
                for (int i = 0; i < 8; i++) {
                    float2 p2 = unpack2(sv2[i]);
                    float  sv = p2.x + p2.y;
                    int cmv = sm.cm[qb + i];
                    sm.Ssh[(qb + i) * 65 + ko + lane] = (cmv && km) ? NEGV : sv;
                }
            }
            // scores for this pair's rows are produced by exactly this warp pair
            asm volatile("bar.sync %0, 64;" :: "r"(pair + 1) : "memory");

            // ---- online softmax (8 lanes per row)
            float lm = -INFINITY;
#pragma unroll
            for (int j = 0; j < 8; j++) lm = fmaxf(lm, sm.Ssh[r8 * 65 + seg * 8 + j]);
            lm = fmaxf(lm, __shfl_xor_sync(0xffffffffu, lm, 4));
            lm = fmaxf(lm, __shfl_xor_sync(0xffffffffu, lm, 2));
            lm = fmaxf(lm, __shfl_xor_sync(0xffffffffu, lm, 1));
            float om = sm.rowmax[r8];
            float nm = fmaxf(om, lm);
            float ls = 0.f;
#pragma unroll
            for (int j = 0; j < 8; j++) {
                int idx = r8 * 65 + seg * 8 + j;
                float p = __expf(sm.Ssh[idx] - nm);
                sm.Ssh[idx] = p;
                ls += p;
            }
            ls += __shfl_xor_sync(0xffffffffu, ls, 4);
            ls += __shfl_xor_sync(0xffffffffu, ls, 2);
            ls += __shfl_xor_sync(0xffffffffu, ls, 1);
            if (seg == 0) {
                float rs = __expf(om - nm);
                sm.rscale[r8] = rs;
                sm.rowsum[r8] = sm.rowsum[r8] * rs + ls;
                sm.rowmax[r8] = nm;
            }
            __syncwarp();   // rows w*4..w*4+3 softmaxed entirely by warp w

            // ---- rescale accumulators
#pragma unroll
            for (int i = 0; i < 4; i++) {
                float rsv = sm.rscale[w * 4 + i];
                unsigned long long rr = pack2(rsv, rsv);
#pragma unroll
                for (int j = 0; j < 4; j++) {
                    acc[i][j][0] = mul2(acc[i][j][0], rr);
                    acc[i][j][1] = mul2(acc[i][j][1], rr);
                }
            }

            // ---- accumulate P @ [V, V^2] : one fma2 per (row, channel)
            // Vs complete: V group retired at ci=2's wait, barriers since.
#pragma unroll 2
            for (int k = 0; k < 64; k++) {
                const float* vrow = &sm.Vs[k * 512 + lane * 4];
                ulonglong2 v0 = *(const ulonglong2*)&vrow[0];
                ulonglong2 v1 = *(const ulonglong2*)&vrow[128];
                ulonglong2 v2 = *(const ulonglong2*)&vrow[256];
                ulonglong2 v3 = *(const ulonglong2*)&vrow[384];
#pragma unroll
                for (int i = 0; i < 4; i++) {
                    float p = sm.Ssh[(w * 4 + i) * 65 + k];
                    unsigned long long pp = pack2(p, p);
                    fma2(acc[i][0][0], pp, v0.x); fma2(acc[i][0][1], pp, v0.y);
                    fma2(acc[i][1][0], pp, v1.x); fma2(acc[i][1][1], pp, v1.y);
                    fma2(acc[i][2][0], pp, v2.x); fma2(acc[i][2][1], pp, v2.y);
                    fma2(acc[i][3][0], pp, v3.x); fma2(acc[i][3][1], pp, v3.y);
                }
            }
            __syncthreads();  // protect Vs/Ks from next k-tile's async issues
        }

        // ---- epilogue: normalize, std = sqrt(relu(m2 - mean^2))
#pragma unroll
        for (int i = 0; i < 4; i++) {
            int row = w * 4 + i;
            float inv = 1.f / sm.rowsum[row];
            size_t base = ((size_t)(b * HW + q0 + row)) * CIN;
#pragma unroll
            for (int j = 0; j < 4; j++) {
                float2 p0 = unpack2(acc[i][j][0]);
                float2 p1 = unpack2(acc[i][j][1]);
                float m0 = p0.x * inv, w0 = p0.y * inv;
                float m1 = p1.x * inv, w1 = p1.y * inv;
                float s0 = sqrtf(fmaxf(w0 - m0 * m0, 0.f));
                float s1 = sqrtf(fmaxf(w1 - m1 * m1, 0.f));
                int c0 = j * 64 + 2 * lane;
                float2 mo; mo.x = m0; mo.y = m1;
                float2 so; so.x = s0; so.y = s1;
                *(float2*)&g_mean[base + c0] = mo;
                *(float2*)&g_std[base + c0]  = so;
            }
        }
        // loop-top __syncthreads orders these accesses vs next tile's init
    }
}

// ---------------- final combine: out[b][c][n] = std*mvn(content)+mean (smem transpose)
__global__ __launch_bounds__(256) void combine_kernel(
    const float* __restrict__ content, float* __restrict__ out)
{
    __shared__ float ms[32][33], ss[32][33];
    const int t  = threadIdx.x;
    const int tx = t & 31, ty = t >> 5;
    const int n0 = blockIdx.x * 32, c0 = blockIdx.y * 32, b = blockIdx.z;
    for (int i = ty; i < 32; i += 8) {
        size_t idx = ((size_t)(b * HW + n0 + i)) * CIN + c0 + tx;
        ms[i][tx] = g_mean[idx];
        ss[i][tx] = g_std[idx];
    }
    __syncthreads();
    for (int i = ty; i < 32; i += 8) {
        int c = c0 + i, n = n0 + tx;
        size_t cidx = ((size_t)(b * CIN + c)) * HW + n;
        float v  = content[cidx];
        float mu = g_cmean[b * CIN + c];
        float rs = g_crstd[b * CIN + c];
        out[cidx] = ss[tx][i] * (v - mu) * rs + ms[tx][i];
    }
}

// ---------------- launch ----------------
extern "C" void kernel_launch(void* const* d_in, const int* in_sizes, int n_in,
                              void* d_out, int out_size)
{
    const float* content     = (const float*)d_in[0];
    const float* style       = (const float*)d_in[1];
    const float* content_key = (const float*)d_in[2];
    const float* style_key   = (const float*)d_in[3];
    const int*   cmask       = (const int*)d_in[4];
    const int*   smask       = (const int*)d_in[5];
    const float* Wf = (const float*)d_in[6];
    const float* bf = (const float*)d_in[7];
    const float* Wg = (const float*)d_in[8];
    const float* bg = (const float*)d_in[9];
    const float* Wh = (const float*)d_in[10];
    const float* bh = (const float*)d_in[11];
    float* out = (float*)d_out;

    void *pFq = nullptr, *pKt = nullptr, *pHvv = nullptr;
    cudaGetSymbolAddress(&pFq, g_Fq);
    cudaGetSymbolAddress(&pKt, g_Kt);
    cudaGetSymbolAddress(&pHvv, g_Hvv);

    const int flash_smem = (int)sizeof(FlashSmem);
    cudaFuncSetAttribute(flash_kernel, cudaFuncAttributeMaxDynamicSharedMemorySize, flash_smem);

    proj_kernel<<<dim3(HW / 64, CKEY / 64, B_), 256>>>(content_key, Wf, bf, (float*)pFq, CKEY, CKEY, 0);
    proj_kernel<<<dim3(HW / 64, CKEY / 64, B_), 256>>>(style_key,   Wg, bg, (float*)pKt, CKEY, CKEY, 0);
    proj_kernel<<<dim3(HW / 64, CIN / 64,  B_), 256>>>(style,       Wh, bh, (float*)pHvv, CIN, CIN, 1);
    stats_kernel<<<dim3(CIN, B_), 256>>>(content);
    ticket_reset_kernel<<<1, 1>>>();
    flash_kernel<<<FLASH_BLOCKS, 256, flash_smem>>>(cmask, smask);
    combine_kernel<<<dim3(HW / 32, CIN / 32, B_), 256>>>(content, out);
}

// round 17
// speedup vs baseline: 1.2183x; 1.2183x over previous
#include <cuda_runtime.h>
#include <math.h>

// Problem constants
#define B_   4
#define CIN  256
#define CKEY 448
#define HW   4096          // N = 64*64 tokens
#define NEGV (-1e15f)

#define NCP   (CKEY / 2)   // 224 c-pairs
#define CPCH  16           // c-pairs per K chunk (32 floats of c)
#define NCHUNK (NCP / CPCH) // 14
#define NTILE (B_ * (HW / 32))   // 512 query tiles
#define FLASH_BLOCKS 152

// ---------------- scratch (static device globals; no allocation) ----------------
// Packed-pair-transposed projections: P[b][cp][np] =
//   (X[2np][2cp], X[2np][2cp+1], X[2np+1][2cp], X[2np+1][2cp+1])
__device__ float4 g_FqP[B_ * NCP * (HW / 2)];   // 29.4 MB
__device__ float4 g_KtP[B_ * NCP * (HW / 2)];   // 29.4 MB
__device__ float  g_Hvv[B_ * HW * 2 * CIN];     // [b][n][2c] interleaved (v, v^2)
__device__ float  g_mean[B_ * HW * CIN];        // [b][n][c]
__device__ float  g_std[B_ * HW * CIN];         // [b][n][c]
__device__ float  g_cmean[B_ * CIN];
__device__ float  g_crstd[B_ * CIN];
__device__ unsigned int g_ticket;

// ---------------- packed f32x2 helpers (FFMA2 path — ptxas never emits these from C++)
__device__ __forceinline__ unsigned long long pack2(float a, float b) {
    unsigned long long r;
    asm("mov.b64 %0, {%1, %2};" : "=l"(r) : "f"(a), "f"(b));
    return r;
}
__device__ __forceinline__ void fma2(unsigned long long& d, unsigned long long a, unsigned long long b) {
    asm("fma.rn.f32x2 %0, %1, %2, %3;" : "=l"(d) : "l"(a), "l"(b), "l"(d));
}
__device__ __forceinline__ unsigned long long mul2(unsigned long long a, unsigned long long b) {
    unsigned long long d;
    asm("mul.rn.f32x2 %0, %1, %2;" : "=l"(d) : "l"(a), "l"(b));
    return d;
}
__device__ __forceinline__ float2 unpack2(unsigned long long v) {
    float2 r;
    asm("mov.b64 {%0, %1}, %2;" : "=f"(r.x), "=f"(r.y) : "l"(v));
    return r;
}

// ---------------- cp.async helpers
__device__ __forceinline__ void cpa16(void* smem_dst, const void* gsrc) {
    unsigned sa = (unsigned)__cvta_generic_to_shared(smem_dst);
    asm volatile("cp.async.cg.shared.global [%0], [%1], 16;" :: "r"(sa), "l"(gsrc));
}
#define CPA_COMMIT()  asm volatile("cp.async.commit_group;")
#define CPA_WAIT(n)   asm volatile("cp.async.wait_group %0;" :: "n"(n))

// ---------------- 1x1 conv == GEMM:  out[n][o] = sum_c x[c][n] * W[o][c] + bias[o]
// mode 0: packed-pair-transposed float4 output (for Fq / Kt)
// mode 1: interleaved (v, v^2) rows of width 2*O (value path)
__global__ __launch_bounds__(256) void proj_kernel(
    const float* __restrict__ x, const float* __restrict__ W,
    const float* __restrict__ bias, void* __restrict__ outp, int C, int O, int mode)
{
    __shared__ float As[16][64];      // [kc][n]
    __shared__ float Bs[16][68];      // [kc][o] padded
    __shared__ float Ts[64][68];      // [n][o] transpose staging (mode 0)
    const int t  = threadIdx.x;
    const int ty = t >> 4, tx = t & 15;
    const int n0 = blockIdx.x * 64, o0 = blockIdx.y * 64, b = blockIdx.z;
    const float* xb = x + (size_t)b * C * HW;

    if (blockIdx.x == 0 && blockIdx.y == 0 && blockIdx.z == 0 && t == 0)
        g_ticket = 0u;   // all proj launches precede flash (stream order)

    unsigned long long acc2[4][2];
#pragma unroll
    for (int i = 0; i < 4; i++) { acc2[i][0] = 0ull; acc2[i][1] = 0ull; }

    for (int c0 = 0; c0 < C; c0 += 16) {
#pragma unroll
        for (int j = 0; j < 4; j++) {
            int idx = t + j * 256;                       // 0..1023
            As[idx >> 6][idx & 63] = xb[(size_t)(c0 + (idx >> 6)) * HW + n0 + (idx & 63)];
        }
#pragma unroll
        for (int j = 0; j < 4; j++) {
            int idx = t + j * 256;
            int kk = idx & 15, o = idx >> 4;
            Bs[kk][o] = W[(size_t)(o0 + o) * C + c0 + kk];
        }
        __syncthreads();
#pragma unroll
        for (int kk = 0; kk < 16; kk++) {
            ulonglong2 bp = *(const ulonglong2*)&Bs[kk][tx * 4];
#pragma unroll
            for (int i = 0; i < 4; i++) {
                float a = As[kk][ty + 16 * i];
                unsigned long long aa = pack2(a, a);
                fma2(acc2[i][0], aa, bp.x);
                fma2(acc2[i][1], aa, bp.y);
            }
        }
        __syncthreads();
    }
    float4 bj = *(const float4*)&bias[o0 + tx * 4];
    if (mode == 1) {
        float* out = (float*)outp;
#pragma unroll
        for (int i = 0; i < 4; i++) {
            float2 l0 = unpack2(acc2[i][0]);
            float2 l1 = unpack2(acc2[i][1]);
            float4 r;
            r.x = l0.x + bj.x; r.y = l0.y + bj.y; r.z = l1.x + bj.z; r.w = l1.y + bj.w;
            size_t row = (size_t)(b * HW) + n0 + ty + 16 * i;
            float4 lo, hi;
            lo.x = r.x; lo.y = r.x * r.x; lo.z = r.y; lo.w = r.y * r.y;
            hi.x = r.z; hi.y = r.z * r.z; hi.z = r.w; hi.w = r.w * r.w;
            size_t base = row * (2 * O) + 2 * (o0 + tx * 4);
            *(float4*)&out[base]     = lo;
            *(float4*)&out[base + 4] = hi;
        }
    } else {
        // stage [n][o] tile in smem, then emit packed-pair-transposed float4s
#pragma unroll
        for (int i = 0; i < 4; i++) {
            float2 l0 = unpack2(acc2[i][0]);
            float2 l1 = unpack2(acc2[i][1]);
            float4 r;
            r.x = l0.x + bj.x; r.y = l0.y + bj.y; r.z = l1.x + bj.z; r.w = l1.y + bj.w;
            *(float4*)&Ts[ty + 16 * i][tx * 4] = r;
        }
        __syncthreads();
        float4* out4 = (float4*)outp;
        const int oc = t >> 3;          // cp-local 0..31
        const int oj = t & 7;           // kp group
        const size_t rowstride = HW / 2;
#pragma unroll
        for (int l = 0; l < 4; l++) {
            int kp = oj * 4 + l;        // 0..31 (n-pair local)
            float4 v;
            v.x = Ts[2 * kp][2 * oc];
            v.y = Ts[2 * kp][2 * oc + 1];
            v.z = Ts[2 * kp + 1][2 * oc];
            v.w = Ts[2 * kp + 1][2 * oc + 1];
            out4[((size_t)b * (O / 2) + (o0 / 2 + oc)) * rowstride + (n0 / 2 + kp)] = v;
        }
    }
}

// ---------------- content per-(b,c) mean / rstd (unbiased var, eps inside sqrt)
__global__ __launch_bounds__(256) void stats_kernel(const float* __restrict__ content)
{
    const int c = blockIdx.x, b = blockIdx.y;
    const float* p = content + ((size_t)(b * CIN + c)) * HW;
    float s = 0.f, s2 = 0.f;
    for (int i = threadIdx.x; i < HW; i += 256) { float v = p[i]; s += v; s2 += v * v; }
#pragma unroll
    for (int o = 16; o > 0; o >>= 1) {
        s  += __shfl_down_sync(0xffffffffu, s,  o);
        s2 += __shfl_down_sync(0xffffffffu, s2, o);
    }
    __shared__ float sh[2][8];
    if ((threadIdx.x & 31) == 0) { sh[0][threadIdx.x >> 5] = s; sh[1][threadIdx.x >> 5] = s2; }
    __syncthreads();
    if (threadIdx.x == 0) {
        float S = 0.f, S2 = 0.f;
#pragma unroll
        for (int w = 0; w < 8; w++) { S += sh[0][w]; S2 += sh[1][w]; }
        float mean = S / (float)HW;
        float var  = (S2 - S * S / (float)HW) / (float)(HW - 1);
        g_cmean[b * CIN + c] = mean;
        g_crstd[b * CIN + c] = rsqrtf(var + 1e-5f);
    }
}

// ---------------- persistent flash attention, dual (mean, m2) accumulators
// QK via pair-packed transposed operands; K chunks are WARP-PRIVATE cp.async
// slices (no cross-warp deps -> no per-chunk __syncthreads; 3 barriers/k-tile).
struct FlashSmem {
    float4 Qt[NCP][16];           // [cp][qp] 57344 B
    float4 Ks[3][8][CPCH][4];     // [buf][warp][cp-local][kp-local] 24576 B
    float  Vs[64 * 512];          // [k][2c] interleaved (v, v^2) 131072 B
    float  Ssh[32 * 65];          // [m][k] padded 8320 B
    float  rowmax[32], rowsum[32], rscale[32];
    int    cm[32];
    int    Msk[64];
    unsigned int ticket;
};

__global__ __launch_bounds__(256, 1) void flash_kernel(
    const int* __restrict__ cmaskg, const int* __restrict__ smaskg)
{
    extern __shared__ __align__(16) char raw[];
    FlashSmem& sm = *reinterpret_cast<FlashSmem*>(raw);
    const int t    = threadIdx.x;
    const int lane = t & 31;
    const int w    = t >> 5;
    const int tq   = t & 7;          // score phase: q-pair lane (qp = tq, tq+8)
    const int tk8  = t >> 3;         // score phase: k-pair 0..31 (= 4w + (lane>>3))
    const int kloc = lane >> 3;      // k-pair local to warp (0..3)
    const int r8   = t >> 3;         // softmax row (0..31)
    const int seg  = t & 7;          // softmax segment

    while (true) {
        if (t == 0) sm.ticket = atomicAdd(&g_ticket, 1u);
        __syncthreads();               // ticket visible; orders vs prior tile's smem use
        const unsigned int tile = sm.ticket;
        if (tile >= NTILE) break;
        const int b  = tile >> 7;
        const int q0 = (tile & 127) * 32;

        // ---- per-tile init: Q tile via cp.async (group Q; retires at first WAIT(2))
        {
            const float4* src = &g_FqP[(size_t)b * NCP * (HW / 2) + q0 / 2];
#pragma unroll
            for (int j = 0; j < 14; j++) {
                int idx = t + j * 256;           // 0..3583
                int row = idx >> 4, col = idx & 15;
                cpa16(&sm.Qt[row][col], &src[(size_t)row * (HW / 2) + col]);
            }
            CPA_COMMIT();
        }
        if (t < 32) {
            sm.cm[t]     = cmaskg[b * HW + q0 + t];
            sm.rowmax[t] = -INFINITY;
            sm.rowsum[t] = 0.f;
        }
        unsigned long long acc[4][4][2];
#pragma unroll
        for (int i = 0; i < 4; i++)
#pragma unroll
            for (int j = 0; j < 4; j++) { acc[i][j][0] = 0ull; acc[i][j][1] = 0ull; }

        const float4* kglob = &g_KtP[(size_t)b * NCP * (HW / 2)];
        const size_t vbase = (size_t)(b * HW) * 512;

        for (int k0 = 0; k0 < HW; k0 += 64) {
            // ---- issue async groups: K chunk0, K chunk1 (warp-private), V tile + mask
#pragma unroll
            for (int cpre = 0; cpre < 2; cpre++) {
                float4* kb = &sm.Ks[cpre][w][0][0];
#pragma unroll
                for (int j = 0; j < 2; j++) {
                    int idx = lane + j * 32;     // 0..63 of this warp's 16x4 slice
                    int row = idx >> 2, col = idx & 3;
                    cpa16(&kb[row * 4 + col],
                          &kglob[(size_t)(cpre * CPCH + row) * (HW / 2) + k0 / 2 + 4 * w + col]);
                }
                CPA_COMMIT();
            }
            {
#pragma unroll
                for (int j = 0; j < 32; j++) {
                    int idx = t + j * 256;       // 0..8191
                    int row = idx >> 7, sg = idx & 127;
                    cpa16(&sm.Vs[row * 512 + sg * 4],
                          &g_Hvv[vbase + (size_t)(k0 + row) * 512 + sg * 4]);
                }
                if (t < 16) cpa16(&sm.Msk[t * 4], &smaskg[b * HW + k0 + t * 4]);
                CPA_COMMIT();
            }

            // ---- S = Q K^T over 14 pipelined chunks (16 c-pairs each)
            unsigned long long sv[8];        // [qi<4][kj<2]
#pragma unroll
            for (int i = 0; i < 8; i++) sv[i] = 0ull;

            for (int ci = 0; ci < NCHUNK; ci++) {
                if (ci < 2)               CPA_WAIT(2);   // ci0 also retires Q on first tile
                else if (ci < NCHUNK - 1) CPA_WAIT(1);   // ci2 retires V+mask as well
                else                      CPA_WAIT(0);
                if (ci == 0) __syncthreads();  // Q (all-thread copy) visible; covers cm too
                else __syncwarp();             // own-warp K slice lanes visible
                if (ci + 2 < NCHUNK) {     // prefetch chunk ci+2 into warp's buffer slice
                    float4* kb = &sm.Ks[(ci + 2) % 3][w][0][0];
#pragma unroll
                    for (int j = 0; j < 2; j++) {
                        int idx = lane + j * 32;
                        int row = idx >> 2, col = idx & 3;
                        cpa16(&kb[row * 4 + col],
                              &kglob[(size_t)((ci + 2) * CPCH + row) * (HW / 2) + k0 / 2 + 4 * w + col]);
                    }
                    CPA_COMMIT();
                }
                const float4* kb = &sm.Ks[ci % 3][w][0][0];
                const int cp0 = ci * CPCH;
#pragma unroll
                for (int cpl = 0; cpl < CPCH; cpl++) {
                    ulonglong2 A0 = *(const ulonglong2*)&sm.Qt[cp0 + cpl][tq];
                    ulonglong2 A1 = *(const ulonglong2*)&sm.Qt[cp0 + cpl][tq + 8];
                    ulonglong2 BV = *(const ulonglong2*)&kb[cpl * 4 + kloc];
                    fma2(sv[0], A0.x, BV.x); fma2(sv[1], A0.x, BV.y);
                    fma2(sv[2], A0.y, BV.x); fma2(sv[3], A0.y, BV.y);
                    fma2(sv[4], A1.x, BV.x); fma2(sv[5], A1.x, BV.y);
                    fma2(sv[6], A1.y, BV.x); fma2(sv[7], A1.y, BV.y);
                }
            }

            // ---- fold c-pairs, store RAW scores (masking deferred to softmax)
            {
                const int qrow[4] = { 2 * tq, 2 * tq + 1, 2 * tq + 16, 2 * tq + 17 };
#pragma unroll
                for (int qi = 0; qi < 4; qi++) {
                    int m = qrow[qi];
                    float2 p0 = unpack2(sv[qi * 2]);
                    float2 p1 = unpack2(sv[qi * 2 + 1]);
                    sm.Ssh[m * 65 + 2 * tk8]     = p0.x + p0.y;
                    sm.Ssh[m * 65 + 2 * tk8 + 1] = p1.x + p1.y;
                }
            }
            __syncthreads();   // scores cross warps; also makes Msk (retired ci=2) visible

            // ---- online softmax with in-read masking (8 lanes per row)
            int cmv = sm.cm[r8];
            float sc[8];
            float lm = -INFINITY;
#pragma unroll
            for (int j = 0; j < 8; j++) {
                float s = sm.Ssh[r8 * 65 + seg * 8 + j];
                if (cmv && sm.Msk[seg * 8 + j] == 0) s = NEGV;
                sc[j] = s;
                lm = fmaxf(lm, s);
            }
            lm = fmaxf(lm, __shfl_xor_sync(0xffffffffu, lm, 4));
            lm = fmaxf(lm, __shfl_xor_sync(0xffffffffu, lm, 2));
            lm = fmaxf(lm, __shfl_xor_sync(0xffffffffu, lm, 1));
            float om = sm.rowmax[r8];
            float nm = fmaxf(om, lm);
            float ls = 0.f;
#pragma unroll
            for (int j = 0; j < 8; j++) {
                float p = __expf(sc[j] - nm);
                sm.Ssh[r8 * 65 + seg * 8 + j] = p;
                ls += p;
            }
            ls += __shfl_xor_sync(0xffffffffu, ls, 4);
            ls += __shfl_xor_sync(0xffffffffu, ls, 2);
            ls += __shfl_xor_sync(0xffffffffu, ls, 1);
            if (seg == 0) {
                float rs = __expf(om - nm);
                sm.rscale[r8] = rs;
                sm.rowsum[r8] = sm.rowsum[r8] * rs + ls;
                sm.rowmax[r8] = nm;
            }
            __syncwarp();   // rows w*4..w*4+3 softmaxed entirely by warp w

            // ---- rescale accumulators
#pragma unroll
            for (int i = 0; i < 4; i++) {
                float rsv = sm.rscale[w * 4 + i];
                unsigned long long rr = pack2(rsv, rsv);
#pragma unroll
                for (int j = 0; j < 4; j++) {
                    acc[i][j][0] = mul2(acc[i][j][0], rr);
                    acc[i][j][1] = mul2(acc[i][j][1], rr);
                }
            }

            // ---- accumulate P @ [V, V^2] : one fma2 per (row, channel)
            // Vs complete: every thread retired V at its ci=2 wait; score barrier since.
#pragma unroll 2
            for (int k = 0; k < 64; k++) {
                const float* vrow = &sm.Vs[k * 512 + lane * 4];
                ulonglong2 v0 = *(const ulonglong2*)&vrow[0];
                ulonglong2 v1 = *(const ulonglong2*)&vrow[128];
                ulonglong2 v2 = *(const ulonglong2*)&vrow[256];
                ulonglong2 v3 = *(const ulonglong2*)&vrow[384];
#pragma unroll
                for (int i = 0; i < 4; i++) {
                    float p = sm.Ssh[(w * 4 + i) * 65 + k];
                    unsigned long long pp = pack2(p, p);
                    fma2(acc[i][0][0], pp, v0.x); fma2(acc[i][0][1], pp, v0.y);
                    fma2(acc[i][1][0], pp, v1.x); fma2(acc[i][1][1], pp, v1.y);
                    fma2(acc[i][2][0], pp, v2.x); fma2(acc[i][2][1], pp, v2.y);
                    fma2(acc[i][3][0], pp, v3.x); fma2(acc[i][3][1], pp, v3.y);
                }
            }
            __syncthreads();  // protect Vs/Ssh from next k-tile's writes
        }

        // ---- epilogue: normalize, std = sqrt(relu(m2 - mean^2))
#pragma unroll
        for (int i = 0; i < 4; i++) {
            int row = w * 4 + i;
            float inv = 1.f / sm.rowsum[row];
            size_t base = ((size_t)(b * HW + q0 + row)) * CIN;
#pragma unroll
            for (int j = 0; j < 4; j++) {
                float2 p0 = unpack2(acc[i][j][0]);
                float2 p1 = unpack2(acc[i][j][1]);
                float m0 = p0.x * inv, w0 = p0.y * inv;
                float m1 = p1.x * inv, w1 = p1.y * inv;
                float s0 = sqrtf(fmaxf(w0 - m0 * m0, 0.f));
                float s1 = sqrtf(fmaxf(w1 - m1 * m1, 0.f));
                int c0 = j * 64 + 2 * lane;
                float2 mo; mo.x = m0; mo.y = m1;
                float2 so; so.x = s0; so.y = s1;
                *(float2*)&g_mean[base + c0] = mo;
                *(float2*)&g_std[base + c0]  = so;
            }
        }
        // loop-top __syncthreads orders these accesses vs next tile's init
    }
}

// ---------------- final combine: out[b][c][n] = std*mvn(content)+mean (smem transpose)
__global__ __launch_bounds__(256) void combine_kernel(
    const float* __restrict__ content, float* __restrict__ out)
{
    __shared__ float ms[32][33], ss[32][33];
    const int t  = threadIdx.x;
    const int tx = t & 31, ty = t >> 5;
    const int n0 = blockIdx.x * 32, c0 = blockIdx.y * 32, b = blockIdx.z;
    for (int i = ty; i < 32; i += 8) {
        size_t idx = ((size_t)(b * HW + n0 + i)) * CIN + c0 + tx;
        ms[i][tx] = g_mean[idx];
        ss[i][tx] = g_std[idx];
    }
    __syncthreads();
    for (int i = ty; i < 32; i += 8) {
        int c = c0 + i, n = n0 + tx;
        size_t cidx = ((size_t)(b * CIN + c)) * HW + n;
        float v  = content[cidx];
        float mu = g_cmean[b * CIN + c];
        float rs = g_crstd[b * CIN + c];
        out[cidx] = ss[tx][i] * (v - mu) * rs + ms[tx][i];
    }
}

// ---------------- launch ----------------
extern "C" void kernel_launch(void* const* d_in, const int* in_sizes, int n_in,
                              void* d_out, int out_size)
{
    const float* content     = (const float*)d_in[0];
    const float* style       = (const float*)d_in[1];
    const float* content_key = (const float*)d_in[2];
    const float* style_key   = (const float*)d_in[3];
    const int*   cmask       = (const int*)d_in[4];
    const int*   smask       = (const int*)d_in[5];
    const float* Wf = (const float*)d_in[6];
    const float* bf = (const float*)d_in[7];
    const float* Wg = (const float*)d_in[8];
    const float* bg = (const float*)d_in[9];
    const float* Wh = (const float*)d_in[10];
    const float* bh = (const float*)d_in[11];
    float* out = (float*)d_out;

    void *pFqP = nullptr, *pKtP = nullptr, *pHvv = nullptr;
    cudaGetSymbolAddress(&pFqP, g_FqP);
    cudaGetSymbolAddress(&pKtP, g_KtP);
    cudaGetSymbolAddress(&pHvv, g_Hvv);

    const int flash_smem = (int)sizeof(FlashSmem);
    cudaFuncSetAttribute(flash_kernel, cudaFuncAttributeMaxDynamicSharedMemorySize, flash_smem);

    // launch order: flash at index 3 (the slot ncu captured last time)
    proj_kernel<<<dim3(HW / 64, CKEY / 64, B_), 256>>>(content_key, Wf, bf, pFqP, CKEY, CKEY, 0);
    proj_kernel<<<dim3(HW / 64, CKEY / 64, B_), 256>>>(style_key,   Wg, bg, pKtP, CKEY, CKEY, 0);
    proj_kernel<<<dim3(HW / 64, CIN / 64,  B_), 256>>>(style,       Wh, bh, pHvv, CIN, CIN, 1);
    flash_kernel<<<FLASH_BLOCKS, 256, flash_smem>>>(cmask, smask);
    stats_kernel<<<dim3(CIN, B_), 256>>>(content);
    combine_kernel<<<dim3(HW / 32, CIN / 32, B_), 256>>>(content, out);
}